// round 6
// baseline (speedup 1.0000x reference)
#include <cuda_runtime.h>
#include <math.h>

#define T_LEN   16
#define C_DIM   192
#define DIN     384
#define DSTATE  16
#define DTRANK  12
#define XP_OUT  44
#define DB_STR  48
#define HW      784
#define NTHR    384
#define TSTR    20

// smem layout (floats), total 13056 floats = 52224 B -> 3 CTAs/SM
//   s_uc [t][c] : [0, 6144)          (also yT [c][t] after scan: [0,7680))
//   s_z  [t][c] : [6144, 12288)      (xn [c][t] 3840 aliased at [6144,9984) pre-B;
//                                     y overwrites z in place during scan)
//   s_db [t][48]: [12288, 13056)
#define OFF_UC 0
#define OFF_Z  6144
#define OFF_XN 6144
#define OFF_DB 12288
#define SMEM_FLOATS 13056

__device__ __forceinline__ float siluf(float v) {
    return __fdividef(v, 1.0f + __expf(-v));
}

__global__ __launch_bounds__(NTHR, 3)
void mamba_fused_kernel(const float* __restrict__ x,
                        const float* __restrict__ norm_w,
                        const float* __restrict__ in_proj_w,   // (192, 768)
                        const float* __restrict__ conv_w,      // (384, 4)
                        const float* __restrict__ conv_b,      // (384,)
                        const float* __restrict__ x_proj_w,    // (384, 44)
                        const float* __restrict__ dt_proj_w,   // (12, 384)
                        const float* __restrict__ dt_proj_b,   // (384,)
                        const float* __restrict__ A_log,       // (384, 16)
                        const float* __restrict__ Dp,          // (384,)
                        const float* __restrict__ out_proj_w,  // (384, 192)
                        float* __restrict__ out)
{
    extern __shared__ float sm[];
    float* s_uc = sm + OFF_UC;
    float* s_z  = sm + OFF_Z;
    float* s_xn = sm + OFF_XN;
    float* s_db = sm + OFF_DB;
    float* s_yT = sm + OFF_UC;   // [c][t] stride TSTR, valid after scan

    const int tid  = threadIdx.x;
    const int lane = tid & 31;
    const int wid  = tid >> 5;

    const int n  = blockIdx.x;
    const int b  = n / HW;
    const int hw = n - b * HW;
    const size_t tstride = (size_t)HW * C_DIM;
    const size_t base0   = ((size_t)b * T_LEN * HW + hw) * C_DIM;

    // ---------------- Phase A: load + RMSNorm -> s_xn[c][t] ----------------
    for (int t = wid; t < T_LEN; t += 12) {
        const float* row = x + base0 + (size_t)t * tstride;
        float v[6];
        float ss = 0.f;
        #pragma unroll
        for (int i = 0; i < 6; i++) { v[i] = row[lane + 32 * i]; ss = fmaf(v[i], v[i], ss); }
        #pragma unroll
        for (int o = 16; o; o >>= 1) ss += __shfl_xor_sync(0xffffffffu, ss, o);
        float nrm = rsqrtf(ss * (1.0f / 192.0f) + 1e-6f);
        #pragma unroll
        for (int i = 0; i < 6; i++) {
            int c = lane + 32 * i;
            s_xn[c * TSTR + t] = v[i] * nrm * norm_w[c];
        }
    }
    __syncthreads();

    // ---------------- Phase B: in_proj -> acc0 (u col tid), acc1 (z) -------
    float acc0[16], acc1[16];
    {
        const float* wp = in_proj_w + tid;
        #pragma unroll
        for (int t = 0; t < 16; t++) { acc0[t] = 0.f; acc1[t] = 0.f; }

        float wa = wp[0], wb = wp[384];
        #pragma unroll 4
        for (int k = 0; k < C_DIM; k++) {
            int kn = k + 1; if (kn >= C_DIM) kn = 0;
            float nwa = wp[kn * 768];
            float nwb = wp[kn * 768 + 384];
            const float4* xp = (const float4*)(s_xn + k * TSTR);
            #pragma unroll
            for (int q = 0; q < 4; q++) {
                float4 xv = xp[q];
                acc0[4*q+0] = fmaf(xv.x, wa, acc0[4*q+0]);
                acc0[4*q+1] = fmaf(xv.y, wa, acc0[4*q+1]);
                acc0[4*q+2] = fmaf(xv.z, wa, acc0[4*q+2]);
                acc0[4*q+3] = fmaf(xv.w, wa, acc0[4*q+3]);
                acc1[4*q+0] = fmaf(xv.x, wb, acc1[4*q+0]);
                acc1[4*q+1] = fmaf(xv.y, wb, acc1[4*q+1]);
                acc1[4*q+2] = fmaf(xv.z, wb, acc1[4*q+2]);
                acc1[4*q+3] = fmaf(xv.w, wb, acc1[4*q+3]);
            }
            wa = nwa; wb = nwb;
        }
    }
    __syncthreads();   // all warps done reading xn before z stores overwrite it

    // ---------------- Phase C: conv in registers; store uc + silu(z) -------
    {
        const int c = tid;
        const float4 cw = *(const float4*)(conv_w + c * 4);
        const float cb = conv_b[c];
        float um3 = 0.f, um2 = 0.f, um1 = 0.f;
        #pragma unroll
        for (int t = 0; t < T_LEN; t++) {
            float u0 = acc0[t];
            float a = cb;
            a = fmaf(um3, cw.x, a);
            a = fmaf(um2, cw.y, a);
            a = fmaf(um1, cw.z, a);
            a = fmaf(u0,  cw.w, a);
            float uc = siluf(a);
            acc0[t] = uc;                       // keep uc in regs for scan
            s_uc[t * DIN + c] = uc;             // smem copy for x_proj
            s_z[t * DIN + c]  = siluf(acc1[t]); // z to smem (read back in scan)
            um3 = um2; um2 = um1; um1 = u0;
        }
    }
    __syncthreads();

    // ---------------- Phase D: x_proj -> s_db ------------------------------
    if (lane < 22) {
        for (int t = wid; t < T_LEN; t += 12) {
            const float* ucr = s_uc + t * DIN;
            const float2* wrow = (const float2*)x_proj_w + lane;  // row stride 22 float2
            float a0 = 0.f, a1 = 0.f;
            #pragma unroll 4
            for (int k = 0; k < DIN; k += 4) {
                float4 uv = *(const float4*)(ucr + k);
                float2 w0 = wrow[(k + 0) * 22];
                float2 w1 = wrow[(k + 1) * 22];
                float2 w2 = wrow[(k + 2) * 22];
                float2 w3 = wrow[(k + 3) * 22];
                a0 = fmaf(uv.x, w0.x, a0); a1 = fmaf(uv.x, w0.y, a1);
                a0 = fmaf(uv.y, w1.x, a0); a1 = fmaf(uv.y, w1.y, a1);
                a0 = fmaf(uv.z, w2.x, a0); a1 = fmaf(uv.z, w2.y, a1);
                a0 = fmaf(uv.w, w3.x, a0); a1 = fmaf(uv.w, w3.y, a1);
            }
            *(float2*)(s_db + t * DB_STR + 2 * lane) = make_float2(a0, a1);
        }
    }
    __syncthreads();

    // ---------------- Phase E: dt_proj + softplus -> acc1 (registers) ------
    // acc1 (z values) already flushed to smem; reuse for dt.
    {
        const int c = tid;
        float wreg[DTRANK];
        #pragma unroll
        for (int r = 0; r < DTRANK; r++) wreg[r] = dt_proj_w[r * DIN + c];
        const float bias = dt_proj_b[c];
        #pragma unroll
        for (int t = 0; t < T_LEN; t++) {
            const float4* dr = (const float4*)(s_db + t * DB_STR);
            float4 d0 = dr[0], d1 = dr[1], d2 = dr[2];
            float a = bias;
            a = fmaf(d0.x, wreg[0],  a);
            a = fmaf(d0.y, wreg[1],  a);
            a = fmaf(d0.z, wreg[2],  a);
            a = fmaf(d0.w, wreg[3],  a);
            a = fmaf(d1.x, wreg[4],  a);
            a = fmaf(d1.y, wreg[5],  a);
            a = fmaf(d1.z, wreg[6],  a);
            a = fmaf(d1.w, wreg[7],  a);
            a = fmaf(d2.x, wreg[8],  a);
            a = fmaf(d2.y, wreg[9],  a);
            a = fmaf(d2.z, wreg[10], a);
            a = fmaf(d2.w, wreg[11], a);
            acc1[t] = (a > 20.f) ? a : log1pf(__expf(a));
        }
    }

    // ---------------- Phase F: selective scan; y overwrites z in place -----
    {
        const int c = tid;
        float A[DSTATE];
        {
            const float4* Ap = (const float4*)(A_log + c * DSTATE);
            #pragma unroll
            for (int q = 0; q < 4; q++) {
                float4 av = Ap[q];
                A[4*q+0] = -__expf(av.x); A[4*q+1] = -__expf(av.y);
                A[4*q+2] = -__expf(av.z); A[4*q+3] = -__expf(av.w);
            }
        }
        float h[DSTATE];
        #pragma unroll
        for (int s = 0; s < DSTATE; s++) h[s] = 0.f;
        const float Dc = Dp[c];

        #pragma unroll 1
        for (int t = 0; t < T_LEN; t++) {
            float dtv = acc1[t];
            float ucv = acc0[t];
            float du  = dtv * ucv;
            const float4* B4 = (const float4*)(s_db + t * DB_STR + DTRANK);
            const float4* C4 = (const float4*)(s_db + t * DB_STR + DTRANK + DSTATE);
            float y = 0.f;
            #pragma unroll
            for (int q = 0; q < 4; q++) {
                float4 Bv = B4[q];
                float4 Cv = C4[q];
                float dA, hb;
                dA = __expf(dtv * A[4*q+0]); hb = fmaf(h[4*q+0], dA, du * Bv.x); h[4*q+0] = hb; y = fmaf(hb, Cv.x, y);
                dA = __expf(dtv * A[4*q+1]); hb = fmaf(h[4*q+1], dA, du * Bv.y); h[4*q+1] = hb; y = fmaf(hb, Cv.y, y);
                dA = __expf(dtv * A[4*q+2]); hb = fmaf(h[4*q+2], dA, du * Bv.z); h[4*q+2] = hb; y = fmaf(hb, Cv.z, y);
                dA = __expf(dtv * A[4*q+3]); hb = fmaf(h[4*q+3], dA, du * Bv.w); h[4*q+3] = hb; y = fmaf(hb, Cv.w, y);
            }
            y = fmaf(ucv, Dc, y);
            s_z[t * DIN + c] = y * s_z[t * DIN + c];   // y in place over z (own element)
        }
    }
    __syncthreads();

    // ---------------- transpose y[t][c] (z region) -> s_yT[c][t] -----------
    {
        const int c = tid;
        float yv[16];
        #pragma unroll
        for (int t = 0; t < T_LEN; t++) yv[t] = s_z[t * DIN + c];
        __syncthreads();   // all reads staged before yT writes clobber uc/z-tail
        float4* dst = (float4*)(s_yT + c * TSTR);
        dst[0] = make_float4(yv[0],  yv[1],  yv[2],  yv[3]);
        dst[1] = make_float4(yv[4],  yv[5],  yv[6],  yv[7]);
        dst[2] = make_float4(yv[8],  yv[9],  yv[10], yv[11]);
        dst[3] = make_float4(yv[12], yv[13], yv[14], yv[15]);
    }
    __syncthreads();

    // ---------------- Phase G: out_proj + residual, pipelined weights ------
    {
        const int c  = (tid < C_DIM) ? tid : (tid - C_DIM);
        const int t0 = (tid < C_DIM) ? 0 : 8;
        const float* wg = out_proj_w + c;
        float acc[8];
        #pragma unroll
        for (int i = 0; i < 8; i++) acc[i] = 0.f;

        float w0 = wg[0], w1 = wg[C_DIM];
        #pragma unroll 2
        for (int k = 0; k < DIN; k += 2) {
            int kn = k + 2; if (kn >= DIN) kn = 0;
            float nw0 = wg[kn * C_DIM];
            float nw1 = wg[kn * C_DIM + C_DIM];

            const float4* yp0 = (const float4*)(s_yT + k * TSTR + t0);
            const float4* yp1 = (const float4*)(s_yT + (k + 1) * TSTR + t0);
            float4 a0 = yp0[0], a1 = yp0[1];
            float4 b0 = yp1[0], b1 = yp1[1];
            acc[0] = fmaf(a0.x, w0, acc[0]);
            acc[1] = fmaf(a0.y, w0, acc[1]);
            acc[2] = fmaf(a0.z, w0, acc[2]);
            acc[3] = fmaf(a0.w, w0, acc[3]);
            acc[4] = fmaf(a1.x, w0, acc[4]);
            acc[5] = fmaf(a1.y, w0, acc[5]);
            acc[6] = fmaf(a1.z, w0, acc[6]);
            acc[7] = fmaf(a1.w, w0, acc[7]);
            acc[0] = fmaf(b0.x, w1, acc[0]);
            acc[1] = fmaf(b0.y, w1, acc[1]);
            acc[2] = fmaf(b0.z, w1, acc[2]);
            acc[3] = fmaf(b0.w, w1, acc[3]);
            acc[4] = fmaf(b1.x, w1, acc[4]);
            acc[5] = fmaf(b1.y, w1, acc[5]);
            acc[6] = fmaf(b1.z, w1, acc[6]);
            acc[7] = fmaf(b1.w, w1, acc[7]);
            w0 = nw0; w1 = nw1;
        }
        #pragma unroll
        for (int i = 0; i < 8; i++) {
            size_t g = base0 + (size_t)(t0 + i) * tstride + c;
            out[g] = x[g] + acc[i];
        }
    }
}

extern "C" void kernel_launch(void* const* d_in, const int* in_sizes, int n_in,
                              void* d_out, int out_size)
{
    (void)in_sizes; (void)n_in; (void)out_size;
    const float* x         = (const float*)d_in[0];
    const float* norm_w    = (const float*)d_in[1];
    const float* in_proj_w = (const float*)d_in[2];
    const float* conv_w    = (const float*)d_in[3];
    const float* conv_b    = (const float*)d_in[4];
    const float* x_proj_w  = (const float*)d_in[5];
    const float* dt_proj_w = (const float*)d_in[6];
    const float* dt_proj_b = (const float*)d_in[7];
    const float* A_log     = (const float*)d_in[8];
    const float* Dp        = (const float*)d_in[9];
    const float* out_pw    = (const float*)d_in[10];
    float* out = (float*)d_out;

    const int smem_bytes = SMEM_FLOATS * (int)sizeof(float);   // 52224 B -> 3 CTAs/SM
    cudaFuncSetAttribute(mamba_fused_kernel,
                         cudaFuncAttributeMaxDynamicSharedMemorySize, smem_bytes);

    dim3 grid(2 * HW);
    dim3 block(NTHR);
    mamba_fused_kernel<<<grid, block, smem_bytes>>>(
        x, norm_w, in_proj_w, conv_w, conv_b, x_proj_w,
        dt_proj_w, dt_proj_b, A_log, Dp, out_pw, out);
}

// round 7
// speedup vs baseline: 1.1741x; 1.1741x over previous
#include <cuda_runtime.h>
#include <math.h>

#define T_LEN   16
#define C_DIM   192
#define DIN     384
#define DSTATE  16
#define DTRANK  12
#define XP_OUT  44
#define DB_STR  48
#define HW      784
#define NTHR    384
#define TSTR    20

// smem layout (floats), total 13056 floats = 52224 B -> 3 CTAs/SM
#define OFF_UC 0        // uc [t][c] 6144 ; later yT [c][t] 7680
#define OFF_Z  6144     // z [t][c] 6144 (xn [c][t] 3840 aliased pre-B; y in place)
#define OFF_XN 6144
#define OFF_DB 12288    // [t][48]
#define SMEM_FLOATS 13056

__device__ __forceinline__ float siluf(float v) {
    return __fdividef(v, 1.0f + __expf(-v));
}

__global__ __launch_bounds__(NTHR, 3)
void mamba_fused_kernel(const float* __restrict__ x,
                        const float* __restrict__ norm_w,
                        const float* __restrict__ in_proj_w,   // (192, 768)
                        const float* __restrict__ conv_w,      // (384, 4)
                        const float* __restrict__ conv_b,      // (384,)
                        const float* __restrict__ x_proj_w,    // (384, 44)
                        const float* __restrict__ dt_proj_w,   // (12, 384)
                        const float* __restrict__ dt_proj_b,   // (384,)
                        const float* __restrict__ A_log,       // (384, 16)
                        const float* __restrict__ Dp,          // (384,)
                        const float* __restrict__ out_proj_w,  // (384, 192)
                        float* __restrict__ out)
{
    extern __shared__ float sm[];
    float* s_uc = sm + OFF_UC;
    float* s_z  = sm + OFF_Z;
    float* s_xn = sm + OFF_XN;
    float* s_db = sm + OFF_DB;
    float* s_yT = sm + OFF_UC;   // [c][t] stride TSTR, valid after transpose

    const int tid  = threadIdx.x;
    const int lane = tid & 31;
    const int wid  = tid >> 5;

    const int n  = blockIdx.x;
    const int b  = n / HW;
    const int hw = n - b * HW;
    const size_t tstride = (size_t)HW * C_DIM;
    const size_t base0   = ((size_t)b * T_LEN * HW + hw) * C_DIM;

    // ---------------- Phase A: load + RMSNorm -> s_xn[c][t] ----------------
    for (int t = wid; t < T_LEN; t += 12) {
        const float* row = x + base0 + (size_t)t * tstride;
        float v[6];
        float ss = 0.f;
        #pragma unroll
        for (int i = 0; i < 6; i++) { v[i] = row[lane + 32 * i]; ss = fmaf(v[i], v[i], ss); }
        #pragma unroll
        for (int o = 16; o; o >>= 1) ss += __shfl_xor_sync(0xffffffffu, ss, o);
        float nrm = rsqrtf(ss * (1.0f / 192.0f) + 1e-6f);
        #pragma unroll
        for (int i = 0; i < 6; i++) {
            int c = lane + 32 * i;
            s_xn[c * TSTR + t] = v[i] * nrm * norm_w[c];
        }
    }
    __syncthreads();

    // ---------------- Phase B: in_proj -> acc0 (u, col tid), acc1 (z) ------
    {
        float acc0[16], acc1[16];
        const float* wp = in_proj_w + tid;
        #pragma unroll
        for (int t = 0; t < 16; t++) { acc0[t] = 0.f; acc1[t] = 0.f; }

        float wa = wp[0], wb = wp[384];
        #pragma unroll 4
        for (int k = 0; k < C_DIM; k++) {
            int kn = k + 1; if (kn >= C_DIM) kn = 0;
            float nwa = wp[kn * 768];
            float nwb = wp[kn * 768 + 384];
            const float4* xp = (const float4*)(s_xn + k * TSTR);
            #pragma unroll
            for (int q = 0; q < 4; q++) {
                float4 xv = xp[q];
                acc0[4*q+0] = fmaf(xv.x, wa, acc0[4*q+0]);
                acc0[4*q+1] = fmaf(xv.y, wa, acc0[4*q+1]);
                acc0[4*q+2] = fmaf(xv.z, wa, acc0[4*q+2]);
                acc0[4*q+3] = fmaf(xv.w, wa, acc0[4*q+3]);
                acc1[4*q+0] = fmaf(xv.x, wb, acc1[4*q+0]);
                acc1[4*q+1] = fmaf(xv.y, wb, acc1[4*q+1]);
                acc1[4*q+2] = fmaf(xv.z, wb, acc1[4*q+2]);
                acc1[4*q+3] = fmaf(xv.w, wb, acc1[4*q+3]);
            }
            wa = nwa; wb = nwb;
        }
        __syncthreads();   // all warps done reading xn before z stores alias it

        // ---------------- Phase C: conv in registers; store uc + silu(z) ---
        const int c = tid;
        const float4 cw = *(const float4*)(conv_w + c * 4);
        const float cb = conv_b[c];
        float um3 = 0.f, um2 = 0.f, um1 = 0.f;
        #pragma unroll
        for (int t = 0; t < T_LEN; t++) {
            float u0 = acc0[t];
            float a = cb;
            a = fmaf(um3, cw.x, a);
            a = fmaf(um2, cw.y, a);
            a = fmaf(um1, cw.z, a);
            a = fmaf(u0,  cw.w, a);
            s_uc[t * DIN + c] = siluf(a);
            s_z[t * DIN + c]  = siluf(acc1[t]);
            um3 = um2; um2 = um1; um1 = u0;
        }
    }
    __syncthreads();

    // ---------------- Phase D: x_proj -> s_db (4 warps x 4 timesteps) ------
    // Weight stream happens 4x per CTA instead of 16x.
    if (wid < 4 && lane < 22) {
        const float2* wrow = (const float2*)x_proj_w + lane;  // row stride 22 float2
        const float* r0 = s_uc + (wid     ) * DIN;
        const float* r1 = s_uc + (wid +  4) * DIN;
        const float* r2 = s_uc + (wid +  8) * DIN;
        const float* r3 = s_uc + (wid + 12) * DIN;
        float a00=0.f,a01=0.f, a10=0.f,a11=0.f, a20=0.f,a21=0.f, a30=0.f,a31=0.f;
        #pragma unroll 2
        for (int k = 0; k < DIN; k += 4) {
            float2 w0 = wrow[(k + 0) * 22];
            float2 w1 = wrow[(k + 1) * 22];
            float2 w2 = wrow[(k + 2) * 22];
            float2 w3 = wrow[(k + 3) * 22];
            float4 u0 = *(const float4*)(r0 + k);
            float4 u1 = *(const float4*)(r1 + k);
            float4 u2 = *(const float4*)(r2 + k);
            float4 u3 = *(const float4*)(r3 + k);
            a00 = fmaf(u0.x, w0.x, a00); a01 = fmaf(u0.x, w0.y, a01);
            a00 = fmaf(u0.y, w1.x, a00); a01 = fmaf(u0.y, w1.y, a01);
            a00 = fmaf(u0.z, w2.x, a00); a01 = fmaf(u0.z, w2.y, a01);
            a00 = fmaf(u0.w, w3.x, a00); a01 = fmaf(u0.w, w3.y, a01);
            a10 = fmaf(u1.x, w0.x, a10); a11 = fmaf(u1.x, w0.y, a11);
            a10 = fmaf(u1.y, w1.x, a10); a11 = fmaf(u1.y, w1.y, a11);
            a10 = fmaf(u1.z, w2.x, a10); a11 = fmaf(u1.z, w2.y, a11);
            a10 = fmaf(u1.w, w3.x, a10); a11 = fmaf(u1.w, w3.y, a11);
            a20 = fmaf(u2.x, w0.x, a20); a21 = fmaf(u2.x, w0.y, a21);
            a20 = fmaf(u2.y, w1.x, a20); a21 = fmaf(u2.y, w1.y, a21);
            a20 = fmaf(u2.z, w2.x, a20); a21 = fmaf(u2.z, w2.y, a21);
            a20 = fmaf(u2.w, w3.x, a20); a21 = fmaf(u2.w, w3.y, a21);
            a30 = fmaf(u3.x, w0.x, a30); a31 = fmaf(u3.x, w0.y, a31);
            a30 = fmaf(u3.y, w1.x, a30); a31 = fmaf(u3.y, w1.y, a31);
            a30 = fmaf(u3.z, w2.x, a30); a31 = fmaf(u3.z, w2.y, a31);
            a30 = fmaf(u3.w, w3.x, a30); a31 = fmaf(u3.w, w3.y, a31);
        }
        *(float2*)(s_db + (wid     ) * DB_STR + 2 * lane) = make_float2(a00, a01);
        *(float2*)(s_db + (wid +  4) * DB_STR + 2 * lane) = make_float2(a10, a11);
        *(float2*)(s_db + (wid +  8) * DB_STR + 2 * lane) = make_float2(a20, a21);
        *(float2*)(s_db + (wid + 12) * DB_STR + 2 * lane) = make_float2(a30, a31);
    }
    __syncthreads();

    // ---------------- Phase E: dt_proj + softplus -> dtv[] registers -------
    float dtv[T_LEN];
    {
        const int c = tid;
        float wreg[DTRANK];
        #pragma unroll
        for (int r = 0; r < DTRANK; r++) wreg[r] = dt_proj_w[r * DIN + c];
        const float bias = dt_proj_b[c];
        #pragma unroll
        for (int t = 0; t < T_LEN; t++) {
            const float4* dr = (const float4*)(s_db + t * DB_STR);
            float4 d0 = dr[0], d1 = dr[1], d2 = dr[2];
            float a = bias;
            a = fmaf(d0.x, wreg[0],  a);
            a = fmaf(d0.y, wreg[1],  a);
            a = fmaf(d0.z, wreg[2],  a);
            a = fmaf(d0.w, wreg[3],  a);
            a = fmaf(d1.x, wreg[4],  a);
            a = fmaf(d1.y, wreg[5],  a);
            a = fmaf(d1.z, wreg[6],  a);
            a = fmaf(d1.w, wreg[7],  a);
            a = fmaf(d2.x, wreg[8],  a);
            a = fmaf(d2.y, wreg[9],  a);
            a = fmaf(d2.z, wreg[10], a);
            a = fmaf(d2.w, wreg[11], a);
            dtv[t] = (a > 20.f) ? a : log1pf(__expf(a));
        }
    }

    // ---------------- Phase F: selective scan; y overwrites z in place -----
    {
        const int c = tid;
        float A[DSTATE];
        {
            const float4* Ap = (const float4*)(A_log + c * DSTATE);
            #pragma unroll
            for (int q = 0; q < 4; q++) {
                float4 av = Ap[q];
                A[4*q+0] = -__expf(av.x); A[4*q+1] = -__expf(av.y);
                A[4*q+2] = -__expf(av.z); A[4*q+3] = -__expf(av.w);
            }
        }
        float h[DSTATE];
        #pragma unroll
        for (int s = 0; s < DSTATE; s++) h[s] = 0.f;
        const float Dc = Dp[c];

        #pragma unroll 1
        for (int t = 0; t < T_LEN; t++) {
            float dt_t = dtv[t];
            float ucv  = s_uc[t * DIN + c];
            float du   = dt_t * ucv;
            const float4* B4 = (const float4*)(s_db + t * DB_STR + DTRANK);
            const float4* C4 = (const float4*)(s_db + t * DB_STR + DTRANK + DSTATE);
            float y = 0.f;
            #pragma unroll
            for (int q = 0; q < 4; q++) {
                float4 Bv = B4[q];
                float4 Cv = C4[q];
                float dA, hb;
                dA = __expf(dt_t * A[4*q+0]); hb = fmaf(h[4*q+0], dA, du * Bv.x); h[4*q+0] = hb; y = fmaf(hb, Cv.x, y);
                dA = __expf(dt_t * A[4*q+1]); hb = fmaf(h[4*q+1], dA, du * Bv.y); h[4*q+1] = hb; y = fmaf(hb, Cv.y, y);
                dA = __expf(dt_t * A[4*q+2]); hb = fmaf(h[4*q+2], dA, du * Bv.z); h[4*q+2] = hb; y = fmaf(hb, Cv.z, y);
                dA = __expf(dt_t * A[4*q+3]); hb = fmaf(h[4*q+3], dA, du * Bv.w); h[4*q+3] = hb; y = fmaf(hb, Cv.w, y);
            }
            y = fmaf(ucv, Dc, y);
            s_z[t * DIN + c] = y * s_z[t * DIN + c];   // y in place over z
        }
    }
    __syncthreads();

    // ---------------- transpose y[t][c] (z region) -> s_yT[c][t] -----------
    {
        const int c = tid;
        float yv[16];
        #pragma unroll
        for (int t = 0; t < T_LEN; t++) yv[t] = s_z[t * DIN + c];
        __syncthreads();   // all reads staged before yT writes clobber uc/z-head
        float4* dst = (float4*)(s_yT + c * TSTR);
        dst[0] = make_float4(yv[0],  yv[1],  yv[2],  yv[3]);
        dst[1] = make_float4(yv[4],  yv[5],  yv[6],  yv[7]);
        dst[2] = make_float4(yv[8],  yv[9],  yv[10], yv[11]);
        dst[3] = make_float4(yv[12], yv[13], yv[14], yv[15]);
    }
    __syncthreads();

    // ---------------- Phase G: out_proj + residual, pipelined weights ------
    {
        const int c  = (tid < C_DIM) ? tid : (tid - C_DIM);
        const int t0 = (tid < C_DIM) ? 0 : 8;
        const float* wg = out_proj_w + c;
        float acc[8];
        #pragma unroll
        for (int i = 0; i < 8; i++) acc[i] = 0.f;

        float w0 = wg[0], w1 = wg[C_DIM];
        #pragma unroll 2
        for (int k = 0; k < DIN; k += 2) {
            int kn = k + 2; if (kn >= DIN) kn = 0;
            float nw0 = wg[kn * C_DIM];
            float nw1 = wg[kn * C_DIM + C_DIM];

            const float4* yp0 = (const float4*)(s_yT + k * TSTR + t0);
            const float4* yp1 = (const float4*)(s_yT + (k + 1) * TSTR + t0);
            float4 a0 = yp0[0], a1 = yp0[1];
            float4 b0 = yp1[0], b1 = yp1[1];
            acc[0] = fmaf(a0.x, w0, acc[0]);
            acc[1] = fmaf(a0.y, w0, acc[1]);
            acc[2] = fmaf(a0.z, w0, acc[2]);
            acc[3] = fmaf(a0.w, w0, acc[3]);
            acc[4] = fmaf(a1.x, w0, acc[4]);
            acc[5] = fmaf(a1.y, w0, acc[5]);
            acc[6] = fmaf(a1.z, w0, acc[6]);
            acc[7] = fmaf(a1.w, w0, acc[7]);
            acc[0] = fmaf(b0.x, w1, acc[0]);
            acc[1] = fmaf(b0.y, w1, acc[1]);
            acc[2] = fmaf(b0.z, w1, acc[2]);
            acc[3] = fmaf(b0.w, w1, acc[3]);
            acc[4] = fmaf(b1.x, w1, acc[4]);
            acc[5] = fmaf(b1.y, w1, acc[5]);
            acc[6] = fmaf(b1.z, w1, acc[6]);
            acc[7] = fmaf(b1.w, w1, acc[7]);
            w0 = nw0; w1 = nw1;
        }
        #pragma unroll
        for (int i = 0; i < 8; i++) {
            size_t g = base0 + (size_t)(t0 + i) * tstride + c;
            out[g] = x[g] + acc[i];
        }
    }
}

extern "C" void kernel_launch(void* const* d_in, const int* in_sizes, int n_in,
                              void* d_out, int out_size)
{
    (void)in_sizes; (void)n_in; (void)out_size;
    const float* x         = (const float*)d_in[0];
    const float* norm_w    = (const float*)d_in[1];
    const float* in_proj_w = (const float*)d_in[2];
    const float* conv_w    = (const float*)d_in[3];
    const float* conv_b    = (const float*)d_in[4];
    const float* x_proj_w  = (const float*)d_in[5];
    const float* dt_proj_w = (const float*)d_in[6];
    const float* dt_proj_b = (const float*)d_in[7];
    const float* A_log     = (const float*)d_in[8];
    const float* Dp        = (const float*)d_in[9];
    const float* out_pw    = (const float*)d_in[10];
    float* out = (float*)d_out;

    const int smem_bytes = SMEM_FLOATS * (int)sizeof(float);   // 52224 B -> 3 CTAs/SM
    cudaFuncSetAttribute(mamba_fused_kernel,
                         cudaFuncAttributeMaxDynamicSharedMemorySize, smem_bytes);

    dim3 grid(2 * HW);
    dim3 block(NTHR);
    mamba_fused_kernel<<<grid, block, smem_bytes>>>(
        x, norm_w, in_proj_w, conv_w, conv_b, x_proj_w,
        dt_proj_w, dt_proj_b, A_log, Dp, out_pw, out);
}